// round 11
// baseline (speedup 1.0000x reference)
#include <cuda_runtime.h>
#include <cuda_bf16.h>
#include <cstdint>
#include <math.h>

#define N_  128
#define T_  1000
#define DO_ 256
#define DS_ 64
#define DU_ 8
#define HE_ 512
#define HG_ 128
#define HD_ 256
#define DN_ 128
#define NT_ (N_*T_)

#define NCH   4                    // pipeline chunks (by sequence)
#define CHN   (N_ / NCH)           // 32 sequences per chunk
#define CHROW (CHN * T_)           // 32000 rows per chunk

typedef unsigned long long u64;

// ---------------- f32x2 packed helpers (GRU/filter) ----------------
__device__ __forceinline__ u64 pk2(float lo, float hi) {
    u64 r; asm("mov.b64 %0, {%1, %2};" : "=l"(r) : "f"(lo), "f"(hi)); return r;
}
__device__ __forceinline__ u64 fma2(u64 a, u64 b, u64 c) {
    u64 d; asm("fma.rn.f32x2 %0, %1, %2, %3;" : "=l"(d) : "l"(a), "l"(b), "l"(c)); return d;
}
__device__ __forceinline__ float2 upk(u64 v) {
    float2 f; asm("mov.b64 {%0, %1}, %2;" : "=f"(f.x), "=f"(f.y) : "l"(v)); return f;
}

// ---------------- cp.async ----------------
__device__ __forceinline__ void cp_async16(uint32_t saddr, const void* gptr) {
    asm volatile("cp.async.cg.shared.global [%0], [%1], 16;" :: "r"(saddr), "l"(gptr));
}
__device__ __forceinline__ void cp_commit() { asm volatile("cp.async.commit_group;"); }

__device__ __forceinline__ uint32_t smem_u32(const void* p) {
    uint32_t a;
    asm("{ .reg .u64 t; cvta.to.shared.u64 t, %1; cvt.u32.u64 %0, t; }" : "=r"(a) : "l"(p));
    return a;
}

// ---------------- mma.sync bf16 helpers ----------------
__device__ __forceinline__ void ldsm_x4(uint32_t& r0, uint32_t& r1, uint32_t& r2, uint32_t& r3,
                                        uint32_t addr) {
    asm volatile("ldmatrix.sync.aligned.m8n8.x4.shared.b16 {%0,%1,%2,%3}, [%4];"
                 : "=r"(r0), "=r"(r1), "=r"(r2), "=r"(r3) : "r"(addr));
}
__device__ __forceinline__ void ldsm_x2(uint32_t& r0, uint32_t& r1, uint32_t addr) {
    asm volatile("ldmatrix.sync.aligned.m8n8.x2.shared.b16 {%0,%1}, [%2];"
                 : "=r"(r0), "=r"(r1) : "r"(addr));
}
__device__ __forceinline__ void mma_bf16(float* d, const uint32_t* a, const uint32_t* b) {
    asm volatile("mma.sync.aligned.m16n8k16.row.col.f32.bf16.bf16.f32 "
                 "{%0,%1,%2,%3}, {%4,%5,%6,%7}, {%8,%9}, {%0,%1,%2,%3};"
                 : "+f"(d[0]), "+f"(d[1]), "+f"(d[2]), "+f"(d[3])
                 : "r"(a[0]), "r"(a[1]), "r"(a[2]), "r"(a[3]), "r"(b[0]), "r"(b[1]));
}

// ---------------- scratch ----------------
__device__ __nv_bfloat16 g_y2[(size_t)NT_ * 512];     // y  dual [hi|lo]
__device__ __nv_bfloat16 g_h2[(size_t)NT_ * 1024];    // h  dual
__device__ __nv_bfloat16 g_a2[(size_t)NT_ * 256];     // a  dual
__device__ __nv_bfloat16 g_hs2[(size_t)NT_ * 256];    // hs dual
__device__ __nv_bfloat16 g_W1t[512 * 768];            // B triple [hi|lo|hi]
__device__ __nv_bfloat16 g_W2t[128 * 1536];
__device__ __nv_bfloat16 g_Wgt[384 * 384];
__device__ __nv_bfloat16 g_Wot[128 * 384];
__device__ float g_a[(size_t)NT_ * DN_];
__device__ float g_gall[(size_t)NT_ * 3 * HG_];
__device__ float g_ab[(size_t)NT_ * DN_];
__device__ float g_maskA[NT_];
__device__ float g_maskB[NT_];
__device__ float g_maskAB[NT_];
__device__ unsigned int g_skeys[(size_t)NT_ * 2];
__device__ unsigned int g_keys[8];
__device__ float g_p;

// ---------------- Threefry2x32 ----------------
__device__ __forceinline__ void tf_round(unsigned int& x0, unsigned int& x1, int r) {
    x0 += x1;
    x1 = __funnelshift_l(x1, x1, r);
    x1 ^= x0;
}
__device__ __forceinline__ uint2 tf2x32(unsigned int k0, unsigned int k1,
                                        unsigned int c0, unsigned int c1) {
    unsigned int ks2 = k0 ^ k1 ^ 0x1BD11BDAu;
    unsigned int x0 = c0 + k0;
    unsigned int x1 = c1 + k1;
    tf_round(x0,x1,13); tf_round(x0,x1,15); tf_round(x0,x1,26); tf_round(x0,x1,6);
    x0 += k1;  x1 += ks2 + 1u;
    tf_round(x0,x1,17); tf_round(x0,x1,29); tf_round(x0,x1,16); tf_round(x0,x1,24);
    x0 += ks2; x1 += k0 + 2u;
    tf_round(x0,x1,13); tf_round(x0,x1,15); tf_round(x0,x1,26); tf_round(x0,x1,6);
    x0 += k0;  x1 += k1 + 3u;
    tf_round(x0,x1,17); tf_round(x0,x1,29); tf_round(x0,x1,16); tf_round(x0,x1,24);
    x0 += k1;  x1 += ks2 + 4u;
    tf_round(x0,x1,13); tf_round(x0,x1,15); tf_round(x0,x1,26); tf_round(x0,x1,6);
    x0 += ks2; x1 += k0 + 5u;
    return make_uint2(x0, x1);
}
__device__ __forceinline__ float bits_to_unit(unsigned int bits) {
    return __uint_as_float((bits >> 9) | 0x3f800000u) - 1.0f;
}
__device__ __forceinline__ float softplusf(float x) {
    return fmaxf(x, 0.0f) + log1pf(expf(-fabsf(x)));
}
__device__ __forceinline__ void bf_split(float v, __nv_bfloat16& hi, __nv_bfloat16& lo) {
    hi = __float2bfloat16(v);
    lo = __float2bfloat16(v - __bfloat162float(hi));
}
__device__ __forceinline__ uint32_t packbf(float x, float y) {
    __nv_bfloat162 h = __floats2bfloat162_rn(x, y);
    return *(uint32_t*)&h;
}

// ---------------- key derivation ----------------
__global__ void key_kernel(const int* seed, const float* dropout) {
    if (threadIdx.x == 0 && blockIdx.x == 0) {
        unsigned int k0 = 0u, k1 = (unsigned int)seed[0];
        uint2 keyF = tf2x32(k0, k1, 0u, 0u);
        uint2 enc  = tf2x32(k0, k1, 0u, 1u);
        uint2 kA = tf2x32(enc.x, enc.y, 0u, 0u);
        uint2 s1 = tf2x32(enc.x, enc.y, 0u, 1u);
        uint2 kB = tf2x32(s1.x, s1.y, 0u, 0u);
        uint2 s2 = tf2x32(s1.x, s1.y, 0u, 1u);
        uint2 kAB = tf2x32(s2.x, s2.y, 0u, 0u);
        g_keys[0] = kA.x;  g_keys[1] = kA.y;
        g_keys[2] = kB.x;  g_keys[3] = kB.y;
        g_keys[4] = kAB.x; g_keys[5] = kAB.y;
        g_keys[6] = keyF.x; g_keys[7] = keyF.y;
        g_p = 1.0f - dropout[0];
    }
}

// ---------------- bernoulli masks ----------------
__global__ void mask_kernel() {
    int idx = blockIdx.x * blockDim.x + threadIdx.x;
    if (idx >= NT_) return;
    float p = g_p;
    unsigned int ci = (unsigned int)idx;
    uint2 ra = tf2x32(g_keys[0], g_keys[1], 0u, ci);
    uint2 rb = tf2x32(g_keys[2], g_keys[3], 0u, ci);
    uint2 rc = tf2x32(g_keys[4], g_keys[5], 0u, ci);
    g_maskA[idx]  = (bits_to_unit(ra.x ^ ra.y) < p) ? 1.0f : 0.0f;
    g_maskB[idx]  = (bits_to_unit(rb.x ^ rb.y) < p) ? 1.0f : 0.0f;
    g_maskAB[idx] = (bits_to_unit(rc.x ^ rc.y) < p) ? 1.0f : 0.0f;
}

// ---------------- serial key chain (side stream) ----------------
__global__ void chain_kernel() {
    int n = blockIdx.x * blockDim.x + threadIdx.x;
    if (n >= N_) return;
    uint2 kk = tf2x32(g_keys[6], g_keys[7], 0u, (unsigned int)n);
    for (int t = 0; t < T_; t++) {
        uint2 sk = tf2x32(kk.x, kk.y, 0u, 1u);
        uint2 nk = tf2x32(kk.x, kk.y, 0u, 0u);
        size_t row = (size_t)n * T_ + t;
        g_skeys[row * 2 + 0] = sk.x;
        g_skeys[row * 2 + 1] = sk.y;
        kk = nk;
    }
}

// ---------------- conversions ----------------
// y fp32 [rows,256] -> dual [hi|lo]; per-chunk (rowoff)
__global__ void conv_y_k(const float* __restrict__ y, int rowoff) {
    int idx = blockIdx.x * 256 + threadIdx.x;
    int m = rowoff + (idx >> 8), k = idx & 255;
    float v = y[(size_t)m * 256 + k];
    __nv_bfloat16 hi, lo; bf_split(v, hi, lo);
    size_t rb = (size_t)m * 512;
    g_y2[rb + k] = hi; g_y2[rb + 256 + k] = lo;
}
// W fp32 [K,Nn] -> Wt [Nn][3K] = [hi|lo|hi]
__global__ void conv_w_k(const float* __restrict__ W, __nv_bfloat16* __restrict__ Wt,
                         int K, int Nn) {
    int idx = blockIdx.x * 256 + threadIdx.x;
    if (idx >= K * Nn) return;
    int k = idx / Nn, n = idx % Nn;
    float v = W[idx];
    __nv_bfloat16 hi, lo; bf_split(v, hi, lo);
    size_t rb = (size_t)n * 3 * K;
    Wt[rb + k] = hi; Wt[rb + K + k] = lo; Wt[rb + 2 * K + k] = hi;
}

// ---------------- HMMA bf16-split GEMM (128x128 tile/CTA, mma.sync) ----------------
#define TG_SMEM (128 * 132 * 4)   // 67584

template <int EPI>
__global__ void __launch_bounds__(256, 2) tgemm_k(
    const __nv_bfloat16* __restrict__ A2, const __nv_bfloat16* __restrict__ B2,
    const float* __restrict__ bias, int Ka, int Nn, int KO, int bmoff,
    float* __restrict__ outF, __nv_bfloat16* __restrict__ outH,
    const float* __restrict__ mask1, const float* __restrict__ mask2,
    const float* __restrict__ aux)
{
    extern __shared__ __align__(16) char smc[];
    const uint32_t sb = smem_u32(smc);
    const int tid = threadIdx.x;
    const int bm = bmoff + blockIdx.y * 128, bn = blockIdx.x * 128;
    const int Kp = 3 * Ka;
    const int Kpa = 2 * Ka;

    uint32_t dsw[4];
    const __nv_bfloat16 *srcA[4], *srcB[4];
#pragma unroll
    for (int i = 0; i < 4; i++) {
        int g = tid + 256 * i;
        int row = g >> 3, c = g & 7;
        uint32_t off = (uint32_t)(row * 128 + c * 16);
        dsw[i] = off ^ ((off >> 3) & 0x70);
        srcA[i] = A2 + (size_t)(bm + row) * Kpa + c * 8;
        srcB[i] = B2 + (size_t)(bn + row) * Kp + c * 8;
    }
    const int KB = Kp >> 6;

    const int w = tid >> 5, l = tid & 31;
    const int wm = (w & 1) * 64, wn = (w >> 1) * 32;

    uint32_t aOff[4], aMsk[4];
#pragma unroll
    for (int mt = 0; mt < 4; mt++) {
        int row = wm + mt * 16 + (l & 15);
        aOff[mt] = (uint32_t)(row * 128 + (l >> 4) * 16);
        aMsk[mt] = ((uint32_t)(row & 7)) << 4;
    }
    uint32_t bOff[4], bMsk[4];
#pragma unroll
    for (int nt = 0; nt < 4; nt++) {
        int row = wn + nt * 8 + (l & 7);
        bOff[nt] = (uint32_t)(row * 128 + ((l >> 3) & 1) * 16);
        bMsk[nt] = ((uint32_t)(row & 7)) << 4;
    }

    float acc[4][4][4];
#pragma unroll
    for (int mt = 0; mt < 4; mt++)
#pragma unroll
        for (int nt = 0; nt < 4; nt++)
#pragma unroll
            for (int e = 0; e < 4; e++) acc[mt][nt][e] = 0.0f;

#pragma unroll
    for (int i = 0; i < 4; i++) cp_async16(sb + dsw[i], srcA[i]);
#pragma unroll
    for (int i = 0; i < 4; i++) cp_async16(sb + 16384 + dsw[i], srcB[i]);
    cp_commit();

    for (int kb = 0; kb < KB; kb++) {
        const int s = kb & 1;
        if (kb + 1 < KB) {
            uint32_t base = sb + (uint32_t)(s ^ 1) * 32768;
            const int ko = (kb + 1) * 64;
            const int pko = (ko < Ka) ? ko : (ko - Ka);
#pragma unroll
            for (int i = 0; i < 4; i++) cp_async16(base + dsw[i], srcA[i] + pko);
#pragma unroll
            for (int i = 0; i < 4; i++) cp_async16(base + 16384 + dsw[i], srcB[i] + ko);
            cp_commit();
            asm volatile("cp.async.wait_group 1;" ::: "memory");
        } else {
            asm volatile("cp.async.wait_group 0;" ::: "memory");
        }
        __syncthreads();

        const uint32_t aB = sb + (uint32_t)s * 32768;
        const uint32_t bB = aB + 16384;
#pragma unroll
        for (int ks = 0; ks < 4; ks++) {
            uint32_t a[4][4], b[4][2];
#pragma unroll
            for (int mt = 0; mt < 4; mt++)
                ldsm_x4(a[mt][0], a[mt][1], a[mt][2], a[mt][3],
                        aB + ((aOff[mt] + ks * 32) ^ aMsk[mt]));
#pragma unroll
            for (int nt = 0; nt < 4; nt++)
                ldsm_x2(b[nt][0], b[nt][1],
                        bB + ((bOff[nt] + ks * 32) ^ bMsk[nt]));
#pragma unroll
            for (int mt = 0; mt < 4; mt++)
#pragma unroll
                for (int nt = 0; nt < 4; nt++)
                    mma_bf16(acc[mt][nt], a[mt], b[nt]);
        }
        __syncthreads();
    }

    float* sOut = (float*)smc;
#pragma unroll
    for (int mt = 0; mt < 4; mt++)
#pragma unroll
        for (int nt = 0; nt < 4; nt++) {
            int r0 = wm + mt * 16 + (l >> 2);
            int c  = wn + nt * 8 + (l & 3) * 2;
            *(float2*)&sOut[r0 * 132 + c]       = make_float2(acc[mt][nt][0], acc[mt][nt][1]);
            *(float2*)&sOut[(r0 + 8) * 132 + c] = make_float2(acc[mt][nt][2], acc[mt][nt][3]);
        }
    __syncthreads();

#pragma unroll
    for (int i = 0; i < 16; i++) {
        int fi = tid + 256 * i;
        int row = fi >> 5;
        int c4 = (fi & 31) << 2;
        const int grow = bm + row;
        const int gc = bn + c4;
        float4 v = *(const float4*)&sOut[row * 132 + c4];
        float4 bs = *(const float4*)(bias + gc);
        float vv[4] = {v.x + bs.x, v.y + bs.y, v.z + bs.z, v.w + bs.w};

        if (EPI == 0) {
#pragma unroll
            for (int e = 0; e < 4; e++) vv[e] = tanhf(vv[e]);
        } else if (EPI == 1 || EPI == 3) {
            if (gc >= 64) {
#pragma unroll
                for (int e = 0; e < 4; e++) vv[e] = -softplusf(vv[e]);
            }
            float m1 = mask1[grow];
#pragma unroll
            for (int e = 0; e < 4; e++) vv[e] *= m1;
            if (EPI == 3) {
                float m2 = mask2[grow];
                float4 ax = *(const float4*)(aux + (size_t)grow * 128 + gc);
                vv[0] = m2 * (ax.x + vv[0]); vv[1] = m2 * (ax.y + vv[1]);
                vv[2] = m2 * (ax.z + vv[2]); vv[3] = m2 * (ax.w + vv[3]);
            }
        }

        if (EPI == 0 || EPI == 1) {
            __nv_bfloat16 hb[4], lb[4];
#pragma unroll
            for (int e = 0; e < 4; e++) bf_split(vv[e], hb[e], lb[e]);
            uint2 hi4 = make_uint2(packbf(__bfloat162float(hb[0]), __bfloat162float(hb[1])),
                                   packbf(__bfloat162float(hb[2]), __bfloat162float(hb[3])));
            uint2 lo4 = make_uint2(packbf(__bfloat162float(lb[0]), __bfloat162float(lb[1])),
                                   packbf(__bfloat162float(lb[2]), __bfloat162float(lb[3])));
            __nv_bfloat16* o = outH + (size_t)grow * (2 * KO) + gc;
            *(uint2*)(o)      = hi4;
            *(uint2*)(o + KO) = lo4;
        }
        if (EPI != 0) {
            *(float4*)(outF + (size_t)grow * Nn + gc) =
                make_float4(vv[0], vv[1], vv[2], vv[3]);
        }
    }
}

// ---------------- GRU: 3 phases, Ug column-resident, f32x2 dots; writes hs2 dual ----------------
__global__ void __launch_bounds__(384, 1) gru_kernel(const float* __restrict__ Ug, int n0) {
    const int n = n0 + blockIdx.x;
    const int j = threadIdx.x;
    __shared__ __align__(16) float h[128];
    __shared__ float rbuf[128], zbuf[128], nbuf[128];
    u64 ug2[64];
#pragma unroll
    for (int k2 = 0; k2 < 64; k2++)
        ug2[k2] = pk2(Ug[(2 * k2) * 384 + j], Ug[(2 * k2 + 1) * 384 + j]);
    if (j < 128) h[j] = 0.0f;

    const float* gbase = g_gall + (size_t)n * T_ * 384;
    float gv = gbase[j];
    __syncthreads();
    for (int t = 0; t < T_; t++) {
        float gvn = 0.0f;
        if (t + 1 < T_) gvn = gbase[(size_t)(t + 1) * 384 + j];

        u64 s4[4] = {0ULL, 0ULL, 0ULL, 0ULL};
#pragma unroll
        for (int k = 0; k < 128; k += 8) {
            ulonglong2 h0 = *(const ulonglong2*)&h[k];
            ulonglong2 h1 = *(const ulonglong2*)&h[k + 4];
            s4[0] = fma2(h0.x, ug2[k / 2],     s4[0]);
            s4[1] = fma2(h0.y, ug2[k / 2 + 1], s4[1]);
            s4[2] = fma2(h1.x, ug2[k / 2 + 2], s4[2]);
            s4[3] = fma2(h1.y, ug2[k / 2 + 3], s4[3]);
        }
        float2 f0 = upk(s4[0]), f1 = upk(s4[1]), f2 = upk(s4[2]), f3 = upk(s4[3]);
        float s = ((f0.x + f0.y) + (f1.x + f1.y)) + ((f2.x + f2.y) + (f3.x + f3.y));
        if (j < 256) {
            float val = 1.0f / (1.0f + expf(-(gv + s)));
            if (j < 128) rbuf[j] = val; else zbuf[j - 128] = val;
        }
        __syncthreads();
        if (j >= 256) {
            nbuf[j - 256] = tanhf(gv + rbuf[j - 256] * s);
        }
        __syncthreads();
        if (j < 128) {
            float z = zbuf[j];
            float hn = (1.0f - z) * nbuf[j] + z * h[j];
            h[j] = hn;
            __nv_bfloat16 hi, lo; bf_split(hn, hi, lo);
            size_t rb = (size_t)(n * T_ + t) * 256;
            g_hs2[rb + j] = hi; g_hs2[rb + 128 + j] = lo;
        }
        gv = gvn;
        __syncthreads();
    }
}

// ---------------- filter: 256 threads, prefetched inputs, f32x2 dots ----------------
__global__ void __launch_bounds__(256, 1) filter_kernel(
    const float* __restrict__ u, const float* __restrict__ Wd1,
    const float* __restrict__ bd1, const float* __restrict__ Wd2,
    const float* __restrict__ bd2, const float* __restrict__ logQ,
    float* __restrict__ out, int n0)
{
    const int n = n0 + blockIdx.x;
    const int tid = threadIdx.x;
    const int q = tid >> 6, j = tid & 63;
    __shared__ __align__(16) float xbuf[72];
    __shared__ __align__(16) float hdyn[256];
    __shared__ float part[4][64];
    __shared__ float vshr[64];
    __shared__ float noi[64];

    u64 wc2[36];
#pragma unroll
    for (int m = 0; m < 36; m++)
        wc2[m] = pk2(Wd1[(2 * m) * 256 + tid], Wd1[(2 * m + 1) * 256 + tid]);
    u64 w2[32];
#pragma unroll
    for (int m = 0; m < 32; m++)
        w2[m] = pk2(Wd2[(q * 64 + 2 * m) * 64 + j], Wd2[(q * 64 + 2 * m + 1) * 64 + j]);
    const float bd1v = bd1[tid];
    const float bd2j = bd2[j];
    const float Qj = softplusf(logQ[j]);

    if (tid < 64) { xbuf[tid] = 0.0f; vshr[tid] = 1.0f; }

    float* outZ = out;
    float* outS = out + (size_t)NT_ * 64;
    float* outP = out + (size_t)NT_ * 192;

    const size_t base = (size_t)n * T_;
    float a1c = 0.0f, a2c = 0.0f, uc = 0.0f;
    unsigned int s0c = 0u, s1c = 0u;
    if (tid < 64) {
        a1c = g_ab[base * 128 + j];
        a2c = g_ab[base * 128 + 64 + j];
        s0c = g_skeys[base * 2];
        s1c = g_skeys[base * 2 + 1];
    } else if (tid < 72) {
        uc = u[base * 8 + (tid - 64)];
    }
    __syncthreads();

    for (int t = 0; t < T_; t++) {
        const size_t row = base + t;
        if (tid < 64) {
            uint2 r = tf2x32(s0c, s1c, 0u, (unsigned int)j);
            float f = bits_to_unit(r.x ^ r.y);
            float uu = __fadd_rn(__fmul_rn(f, 2.0f), -0.99999994f);
            uu = fmaxf(uu, -0.99999994f);
            noi[j] = 1.41421356f * erfinvf(uu);
        } else if (tid < 72) {
            xbuf[tid] = uc;
        }
        __syncthreads();

        float a1n = 0.0f, a2n = 0.0f, un = 0.0f;
        unsigned int s0n = 0u, s1n = 0u;
        if (t + 1 < T_) {
            if (tid < 64) {
                a1n = g_ab[(row + 1) * 128 + j];
                a2n = g_ab[(row + 1) * 128 + 64 + j];
                s0n = g_skeys[(row + 1) * 2];
                s1n = g_skeys[(row + 1) * 2 + 1];
            } else if (tid < 72) {
                un = u[(row + 1) * 8 + (tid - 64)];
            }
        }

        u64 s2a = pk2(bd1v, 0.0f), s2b = 0ULL;
#pragma unroll
        for (int k = 0; k < 72; k += 4) {
            ulonglong2 xv = *(const ulonglong2*)&xbuf[k];
            s2a = fma2(xv.x, wc2[k / 2],     s2a);
            s2b = fma2(xv.y, wc2[k / 2 + 1], s2b);
        }
        {
            float2 fa = upk(s2a), fb = upk(s2b);
            hdyn[tid] = tanhf((fa.x + fa.y) + (fb.x + fb.y));
        }
        __syncthreads();

        u64 p2a = 0ULL, p2b = 0ULL;
#pragma unroll
        for (int k = 0; k < 64; k += 4) {
            ulonglong2 hv = *(const ulonglong2*)&hdyn[q * 64 + k];
            p2a = fma2(hv.x, w2[k / 2],     p2a);
            p2b = fma2(hv.y, w2[k / 2 + 1], p2b);
        }
        {
            float2 fa = upk(p2a), fb = upk(p2b);
            part[q][j] = (fa.x + fa.y) + (fb.x + fb.y);
        }
        __syncthreads();

        if (tid < 64) {
            float mp = ((part[0][j] + part[1][j]) + (part[2][j] + part[3][j])) + bd2j;
            float vp = vshr[j] + Qj;
            float Jp = 1.0f / vp;
            float hp = mp * Jp;
            float Jpost = Jp - 2.0f * a2c;
            float vn = 1.0f / Jpost;
            float mn = (hp + a1c) * vn;
            float zz = mn + sqrtf(vn) * noi[j];
            xbuf[j] = mn;
            vshr[j] = vn;
            outZ[row * 64 + j] = zz;
            outS[row * 128 + j] = mn;
            outS[row * 128 + 64 + j] = vn;
            outP[row * 128 + j] = mp;
            outP[row * 128 + 64 + j] = vp;
        }
        a1c = a1n; a2c = a2n; s0c = s0n; s1c = s1n; uc = un;
        __syncthreads();
    }
}

// ---------------- host launcher ----------------
extern "C" void kernel_launch(void* const* d_in, const int* in_sizes, int n_in,
                              void* d_out, int out_size) {
    (void)in_sizes; (void)n_in; (void)out_size;
    const int*   seed    = (const int*)d_in[3];
    const float* dropout = (const float*)d_in[4];
    const float* y   = (const float*)d_in[1];
    const float* u   = (const float*)d_in[2];
    const float* W1  = (const float*)d_in[5];
    const float* b1  = (const float*)d_in[6];
    const float* W2  = (const float*)d_in[7];
    const float* b2  = (const float*)d_in[8];
    const float* Wg  = (const float*)d_in[9];
    const float* Ug  = (const float*)d_in[10];
    const float* bg  = (const float*)d_in[11];
    const float* Wo  = (const float*)d_in[12];
    const float* bo  = (const float*)d_in[13];
    const float* Wd1 = (const float*)d_in[14];
    const float* bd1 = (const float*)d_in[15];
    const float* Wd2 = (const float*)d_in[16];
    const float* bd2 = (const float*)d_in[17];
    const float* logQ= (const float*)d_in[18];
    float* out = (float*)d_out;

    float *pa, *pg, *pab, *pmA, *pmB, *pmAB;
    __nv_bfloat16 *py2, *ph2, *pa2, *phs2, *pW1t, *pW2t, *pWgt, *pWot;
    cudaGetSymbolAddress((void**)&pa,   g_a);
    cudaGetSymbolAddress((void**)&pg,   g_gall);
    cudaGetSymbolAddress((void**)&pab,  g_ab);
    cudaGetSymbolAddress((void**)&pmA,  g_maskA);
    cudaGetSymbolAddress((void**)&pmB,  g_maskB);
    cudaGetSymbolAddress((void**)&pmAB, g_maskAB);
    cudaGetSymbolAddress((void**)&py2,  g_y2);
    cudaGetSymbolAddress((void**)&ph2,  g_h2);
    cudaGetSymbolAddress((void**)&pa2,  g_a2);
    cudaGetSymbolAddress((void**)&phs2, g_hs2);
    cudaGetSymbolAddress((void**)&pW1t, g_W1t);
    cudaGetSymbolAddress((void**)&pW2t, g_W2t);
    cudaGetSymbolAddress((void**)&pWgt, g_Wgt);
    cudaGetSymbolAddress((void**)&pWot, g_Wot);

    static cudaStream_t s_chain = nullptr, sG = nullptr, sF = nullptr;
    static cudaEvent_t ev_fork = nullptr, ev_join = nullptr, ev_fdone = nullptr;
    static cudaEvent_t evGemm[NCH], evGru[NCH];
    if (s_chain == nullptr) {
        cudaStreamCreateWithFlags(&s_chain, cudaStreamNonBlocking);
        cudaStreamCreateWithFlags(&sG, cudaStreamNonBlocking);
        cudaStreamCreateWithFlags(&sF, cudaStreamNonBlocking);
        cudaEventCreateWithFlags(&ev_fork, cudaEventDisableTiming);
        cudaEventCreateWithFlags(&ev_join, cudaEventDisableTiming);
        cudaEventCreateWithFlags(&ev_fdone, cudaEventDisableTiming);
        for (int c = 0; c < NCH; c++) {
            cudaEventCreateWithFlags(&evGemm[c], cudaEventDisableTiming);
            cudaEventCreateWithFlags(&evGru[c], cudaEventDisableTiming);
        }
        cudaFuncSetAttribute(tgemm_k<0>, cudaFuncAttributeMaxDynamicSharedMemorySize, TG_SMEM);
        cudaFuncSetAttribute(tgemm_k<1>, cudaFuncAttributeMaxDynamicSharedMemorySize, TG_SMEM);
        cudaFuncSetAttribute(tgemm_k<2>, cudaFuncAttributeMaxDynamicSharedMemorySize, TG_SMEM);
        cudaFuncSetAttribute(tgemm_k<3>, cudaFuncAttributeMaxDynamicSharedMemorySize, TG_SMEM);
    }

    key_kernel<<<1, 1>>>(seed, dropout);

    // fork: serial Threefry chain overlaps the pipeline
    cudaEventRecord(ev_fork, 0);
    cudaStreamWaitEvent(s_chain, ev_fork, 0);
    chain_kernel<<<1, 128, 0, s_chain>>>();
    cudaEventRecord(ev_join, s_chain);

    mask_kernel<<<(NT_ + 255) / 256, 256>>>();
    conv_w_k<<<(DO_ * HE_ + 255) / 256, 256>>>(W1, pW1t, DO_, HE_);
    conv_w_k<<<(HE_ * DN_ + 255) / 256, 256>>>(W2, pW2t, HE_, DN_);
    conv_w_k<<<(DN_ * 384 + 255) / 256, 256>>>(Wg, pWgt, DN_, 384);
    conv_w_k<<<(HG_ * DN_ + 255) / 256, 256>>>(Wo, pWot, HG_, DN_);

    // ---- chunked pipeline over sequence blocks ----
    for (int c = 0; c < NCH; c++) {
        const int n0 = c * CHN;
        const int rowoff = n0 * T_;

        // stage A (stream 0): conv_y + 3 GEMMs for this chunk
        conv_y_k<<<CHROW, 256>>>(y, rowoff);
        tgemm_k<0><<<dim3(4, CHROW / 128), 256, TG_SMEM>>>(py2, pW1t, b1, DO_, HE_, HE_, rowoff,
                                                           nullptr, ph2, nullptr, nullptr, nullptr);
        tgemm_k<1><<<dim3(1, CHROW / 128), 256, TG_SMEM>>>(ph2, pW2t, b2, HE_, DN_, DN_, rowoff,
                                                           pa, pa2, pmA, nullptr, nullptr);
        tgemm_k<2><<<dim3(3, CHROW / 128), 256, TG_SMEM>>>(pa2, pWgt, bg, DN_, 384, 0, rowoff,
                                                           pg, nullptr, nullptr, nullptr, nullptr);
        cudaEventRecord(evGemm[c], 0);

        // stage B (stream G): GRU scan for this chunk
        cudaStreamWaitEvent(sG, evGemm[c], 0);
        gru_kernel<<<CHN, 384, 0, sG>>>(Ug, n0);
        cudaEventRecord(evGru[c], sG);

        // stage C (stream F): tgemm3 + filter for this chunk
        cudaStreamWaitEvent(sF, evGru[c], 0);
        if (c == 0) cudaStreamWaitEvent(sF, ev_join, 0);  // skeys ready
        tgemm_k<3><<<dim3(1, CHROW / 128), 256, TG_SMEM, sF>>>(phs2, pWot, bo, HG_, DN_, 0, rowoff,
                                                               pab, nullptr, pmB, pmAB, pa);
        filter_kernel<<<CHN, 256, 0, sF>>>(u, Wd1, bd1, Wd2, bd2, logQ, out, n0);
    }

    // join all side streams back into the capture stream
    cudaEventRecord(ev_fdone, sF);
    cudaStreamWaitEvent(0, ev_fdone, 0);
}

// round 13
// speedup vs baseline: 1.7070x; 1.7070x over previous
#include <cuda_runtime.h>
#include <cuda_bf16.h>
#include <cstdint>
#include <math.h>

#define N_  128
#define T_  1000
#define DO_ 256
#define DS_ 64
#define DU_ 8
#define HE_ 512
#define HG_ 128
#define HD_ 256
#define DN_ 128
#define NT_ (N_*T_)

#define NCH   4                    // pipeline chunks (by sequence)
#define CHN   (N_ / NCH)           // 32 sequences per chunk
#define CHROW (CHN * T_)           // 32000 rows per chunk

typedef unsigned long long u64;

// ---------------- f32x2 packed helpers (GRU/filter) ----------------
__device__ __forceinline__ u64 pk2(float lo, float hi) {
    u64 r; asm("mov.b64 %0, {%1, %2};" : "=l"(r) : "f"(lo), "f"(hi)); return r;
}
__device__ __forceinline__ u64 fma2(u64 a, u64 b, u64 c) {
    u64 d; asm("fma.rn.f32x2 %0, %1, %2, %3;" : "=l"(d) : "l"(a), "l"(b), "l"(c)); return d;
}
__device__ __forceinline__ float2 upk(u64 v) {
    float2 f; asm("mov.b64 {%0, %1}, %2;" : "=f"(f.x), "=f"(f.y) : "l"(v)); return f;
}

// ---------------- cp.async ----------------
__device__ __forceinline__ void cp_async16(uint32_t saddr, const void* gptr) {
    asm volatile("cp.async.cg.shared.global [%0], [%1], 16;" :: "r"(saddr), "l"(gptr));
}
__device__ __forceinline__ void cp_commit() { asm volatile("cp.async.commit_group;"); }

__device__ __forceinline__ uint32_t smem_u32(const void* p) {
    uint32_t a;
    asm("{ .reg .u64 t; cvta.to.shared.u64 t, %1; cvt.u32.u64 %0, t; }" : "=r"(a) : "l"(p));
    return a;
}

// ---------------- mma.sync bf16 helpers ----------------
__device__ __forceinline__ void ldsm_x4(uint32_t& r0, uint32_t& r1, uint32_t& r2, uint32_t& r3,
                                        uint32_t addr) {
    asm volatile("ldmatrix.sync.aligned.m8n8.x4.shared.b16 {%0,%1,%2,%3}, [%4];"
                 : "=r"(r0), "=r"(r1), "=r"(r2), "=r"(r3) : "r"(addr));
}
__device__ __forceinline__ void ldsm_x2(uint32_t& r0, uint32_t& r1, uint32_t addr) {
    asm volatile("ldmatrix.sync.aligned.m8n8.x2.shared.b16 {%0,%1}, [%2];"
                 : "=r"(r0), "=r"(r1) : "r"(addr));
}
__device__ __forceinline__ void mma_bf16(float* d, const uint32_t* a, const uint32_t* b) {
    asm volatile("mma.sync.aligned.m16n8k16.row.col.f32.bf16.bf16.f32 "
                 "{%0,%1,%2,%3}, {%4,%5,%6,%7}, {%8,%9}, {%0,%1,%2,%3};"
                 : "+f"(d[0]), "+f"(d[1]), "+f"(d[2]), "+f"(d[3])
                 : "r"(a[0]), "r"(a[1]), "r"(a[2]), "r"(a[3]), "r"(b[0]), "r"(b[1]));
}

// ---------------- scratch ----------------
__device__ __nv_bfloat16 g_y2[(size_t)NT_ * 512];     // y  dual [hi|lo]
__device__ __nv_bfloat16 g_h2[(size_t)NT_ * 1024];    // h  dual
__device__ __nv_bfloat16 g_a2[(size_t)NT_ * 256];     // a  dual
__device__ __nv_bfloat16 g_hs2[(size_t)NT_ * 256];    // hs dual
__device__ __nv_bfloat16 g_W1t[512 * 768];            // B triple [hi|lo|hi]
__device__ __nv_bfloat16 g_W2t[128 * 1536];
__device__ __nv_bfloat16 g_Wgt[384 * 384];
__device__ __nv_bfloat16 g_Wot[128 * 384];
__device__ float g_a[(size_t)NT_ * DN_];
__device__ float g_gall[(size_t)NT_ * 3 * HG_];
__device__ float g_ab[(size_t)NT_ * DN_];
__device__ float g_noise[(size_t)NT_ * 64];           // precomputed gaussian noise
__device__ float g_maskA[NT_];
__device__ float g_maskB[NT_];
__device__ float g_maskAB[NT_];
__device__ unsigned int g_skeys[(size_t)NT_ * 2];
__device__ unsigned int g_keys[8];
__device__ float g_p;

// ---------------- Threefry2x32 ----------------
__device__ __forceinline__ void tf_round(unsigned int& x0, unsigned int& x1, int r) {
    x0 += x1;
    x1 = __funnelshift_l(x1, x1, r);
    x1 ^= x0;
}
__device__ __forceinline__ uint2 tf2x32(unsigned int k0, unsigned int k1,
                                        unsigned int c0, unsigned int c1) {
    unsigned int ks2 = k0 ^ k1 ^ 0x1BD11BDAu;
    unsigned int x0 = c0 + k0;
    unsigned int x1 = c1 + k1;
    tf_round(x0,x1,13); tf_round(x0,x1,15); tf_round(x0,x1,26); tf_round(x0,x1,6);
    x0 += k1;  x1 += ks2 + 1u;
    tf_round(x0,x1,17); tf_round(x0,x1,29); tf_round(x0,x1,16); tf_round(x0,x1,24);
    x0 += ks2; x1 += k0 + 2u;
    tf_round(x0,x1,13); tf_round(x0,x1,15); tf_round(x0,x1,26); tf_round(x0,x1,6);
    x0 += k0;  x1 += k1 + 3u;
    tf_round(x0,x1,17); tf_round(x0,x1,29); tf_round(x0,x1,16); tf_round(x0,x1,24);
    x0 += k1;  x1 += ks2 + 4u;
    tf_round(x0,x1,13); tf_round(x0,x1,15); tf_round(x0,x1,26); tf_round(x0,x1,6);
    x0 += ks2; x1 += k0 + 5u;
    return make_uint2(x0, x1);
}
__device__ __forceinline__ float bits_to_unit(unsigned int bits) {
    return __uint_as_float((bits >> 9) | 0x3f800000u) - 1.0f;
}
__device__ __forceinline__ float softplusf(float x) {
    return fmaxf(x, 0.0f) + log1pf(expf(-fabsf(x)));
}
__device__ __forceinline__ void bf_split(float v, __nv_bfloat16& hi, __nv_bfloat16& lo) {
    hi = __float2bfloat16(v);
    lo = __float2bfloat16(v - __bfloat162float(hi));
}
__device__ __forceinline__ uint32_t packbf(float x, float y) {
    __nv_bfloat162 h = __floats2bfloat162_rn(x, y);
    return *(uint32_t*)&h;
}

// ---------------- key derivation ----------------
__global__ void key_kernel(const int* seed, const float* dropout) {
    if (threadIdx.x == 0 && blockIdx.x == 0) {
        unsigned int k0 = 0u, k1 = (unsigned int)seed[0];
        uint2 keyF = tf2x32(k0, k1, 0u, 0u);
        uint2 enc  = tf2x32(k0, k1, 0u, 1u);
        uint2 kA = tf2x32(enc.x, enc.y, 0u, 0u);
        uint2 s1 = tf2x32(enc.x, enc.y, 0u, 1u);
        uint2 kB = tf2x32(s1.x, s1.y, 0u, 0u);
        uint2 s2 = tf2x32(s1.x, s1.y, 0u, 1u);
        uint2 kAB = tf2x32(s2.x, s2.y, 0u, 0u);
        g_keys[0] = kA.x;  g_keys[1] = kA.y;
        g_keys[2] = kB.x;  g_keys[3] = kB.y;
        g_keys[4] = kAB.x; g_keys[5] = kAB.y;
        g_keys[6] = keyF.x; g_keys[7] = keyF.y;
        g_p = 1.0f - dropout[0];
    }
}

// ---------------- bernoulli masks ----------------
__global__ void mask_kernel() {
    int idx = blockIdx.x * blockDim.x + threadIdx.x;
    if (idx >= NT_) return;
    float p = g_p;
    unsigned int ci = (unsigned int)idx;
    uint2 ra = tf2x32(g_keys[0], g_keys[1], 0u, ci);
    uint2 rb = tf2x32(g_keys[2], g_keys[3], 0u, ci);
    uint2 rc = tf2x32(g_keys[4], g_keys[5], 0u, ci);
    g_maskA[idx]  = (bits_to_unit(ra.x ^ ra.y) < p) ? 1.0f : 0.0f;
    g_maskB[idx]  = (bits_to_unit(rb.x ^ rb.y) < p) ? 1.0f : 0.0f;
    g_maskAB[idx] = (bits_to_unit(rc.x ^ rc.y) < p) ? 1.0f : 0.0f;
}

// ---------------- serial key chain (side stream) ----------------
__global__ void chain_kernel() {
    int n = blockIdx.x * blockDim.x + threadIdx.x;
    if (n >= N_) return;
    uint2 kk = tf2x32(g_keys[6], g_keys[7], 0u, (unsigned int)n);
    for (int t = 0; t < T_; t++) {
        uint2 sk = tf2x32(kk.x, kk.y, 0u, 1u);
        uint2 nk = tf2x32(kk.x, kk.y, 0u, 0u);
        size_t row = (size_t)n * T_ + t;
        g_skeys[row * 2 + 0] = sk.x;
        g_skeys[row * 2 + 1] = sk.y;
        kk = nk;
    }
}

// ---------------- noise precompute (side stream; off filter's critical path) ----------------
__global__ void noise_kernel() {
    size_t idx = (size_t)blockIdx.x * 256 + threadIdx.x;   // NT*64 total
    size_t row = idx >> 6;
    unsigned int j = (unsigned int)(idx & 63);
    uint2 r = tf2x32(g_skeys[row * 2], g_skeys[row * 2 + 1], 0u, j);
    float f = bits_to_unit(r.x ^ r.y);
    float uu = __fadd_rn(__fmul_rn(f, 2.0f), -0.99999994f);
    uu = fmaxf(uu, -0.99999994f);
    g_noise[idx] = 1.41421356f * erfinvf(uu);
}

// ---------------- conversions ----------------
__global__ void conv_y_k(const float* __restrict__ y, int rowoff) {
    int idx = blockIdx.x * 256 + threadIdx.x;
    int m = rowoff + (idx >> 8), k = idx & 255;
    float v = y[(size_t)m * 256 + k];
    __nv_bfloat16 hi, lo; bf_split(v, hi, lo);
    size_t rb = (size_t)m * 512;
    g_y2[rb + k] = hi; g_y2[rb + 256 + k] = lo;
}
__global__ void conv_w_k(const float* __restrict__ W, __nv_bfloat16* __restrict__ Wt,
                         int K, int Nn) {
    int idx = blockIdx.x * 256 + threadIdx.x;
    if (idx >= K * Nn) return;
    int k = idx / Nn, n = idx % Nn;
    float v = W[idx];
    __nv_bfloat16 hi, lo; bf_split(v, hi, lo);
    size_t rb = (size_t)n * 3 * K;
    Wt[rb + k] = hi; Wt[rb + K + k] = lo; Wt[rb + 2 * K + k] = hi;
}

// ---------------- HMMA bf16-split GEMM (128x128 tile/CTA, mma.sync) ----------------
#define TG_SMEM (128 * 132 * 4)   // 67584

template <int EPI>
__global__ void __launch_bounds__(256, 2) tgemm_k(
    const __nv_bfloat16* __restrict__ A2, const __nv_bfloat16* __restrict__ B2,
    const float* __restrict__ bias, int Ka, int Nn, int KO, int bmoff,
    float* __restrict__ outF, __nv_bfloat16* __restrict__ outH,
    const float* __restrict__ mask1, const float* __restrict__ mask2,
    const float* __restrict__ aux)
{
    extern __shared__ __align__(16) char smc[];
    const uint32_t sb = smem_u32(smc);
    const int tid = threadIdx.x;
    const int bm = bmoff + blockIdx.y * 128, bn = blockIdx.x * 128;
    const int Kp = 3 * Ka;
    const int Kpa = 2 * Ka;

    uint32_t dsw[4];
    const __nv_bfloat16 *srcA[4], *srcB[4];
#pragma unroll
    for (int i = 0; i < 4; i++) {
        int g = tid + 256 * i;
        int row = g >> 3, c = g & 7;
        uint32_t off = (uint32_t)(row * 128 + c * 16);
        dsw[i] = off ^ ((off >> 3) & 0x70);
        srcA[i] = A2 + (size_t)(bm + row) * Kpa + c * 8;
        srcB[i] = B2 + (size_t)(bn + row) * Kp + c * 8;
    }
    const int KB = Kp >> 6;

    const int w = tid >> 5, l = tid & 31;
    const int wm = (w & 1) * 64, wn = (w >> 1) * 32;

    uint32_t aOff[4], aMsk[4];
#pragma unroll
    for (int mt = 0; mt < 4; mt++) {
        int row = wm + mt * 16 + (l & 15);
        aOff[mt] = (uint32_t)(row * 128 + (l >> 4) * 16);
        aMsk[mt] = ((uint32_t)(row & 7)) << 4;
    }
    uint32_t bOff[4], bMsk[4];
#pragma unroll
    for (int nt = 0; nt < 4; nt++) {
        int row = wn + nt * 8 + (l & 7);
        bOff[nt] = (uint32_t)(row * 128 + ((l >> 3) & 1) * 16);
        bMsk[nt] = ((uint32_t)(row & 7)) << 4;
    }

    float acc[4][4][4];
#pragma unroll
    for (int mt = 0; mt < 4; mt++)
#pragma unroll
        for (int nt = 0; nt < 4; nt++)
#pragma unroll
            for (int e = 0; e < 4; e++) acc[mt][nt][e] = 0.0f;

#pragma unroll
    for (int i = 0; i < 4; i++) cp_async16(sb + dsw[i], srcA[i]);
#pragma unroll
    for (int i = 0; i < 4; i++) cp_async16(sb + 16384 + dsw[i], srcB[i]);
    cp_commit();

    for (int kb = 0; kb < KB; kb++) {
        const int s = kb & 1;
        if (kb + 1 < KB) {
            uint32_t base = sb + (uint32_t)(s ^ 1) * 32768;
            const int ko = (kb + 1) * 64;
            const int pko = (ko < Ka) ? ko : (ko - Ka);
#pragma unroll
            for (int i = 0; i < 4; i++) cp_async16(base + dsw[i], srcA[i] + pko);
#pragma unroll
            for (int i = 0; i < 4; i++) cp_async16(base + 16384 + dsw[i], srcB[i] + ko);
            cp_commit();
            asm volatile("cp.async.wait_group 1;" ::: "memory");
        } else {
            asm volatile("cp.async.wait_group 0;" ::: "memory");
        }
        __syncthreads();

        const uint32_t aB = sb + (uint32_t)s * 32768;
        const uint32_t bB = aB + 16384;
#pragma unroll
        for (int ks = 0; ks < 4; ks++) {
            uint32_t a[4][4], b[4][2];
#pragma unroll
            for (int mt = 0; mt < 4; mt++)
                ldsm_x4(a[mt][0], a[mt][1], a[mt][2], a[mt][3],
                        aB + ((aOff[mt] + ks * 32) ^ aMsk[mt]));
#pragma unroll
            for (int nt = 0; nt < 4; nt++)
                ldsm_x2(b[nt][0], b[nt][1],
                        bB + ((bOff[nt] + ks * 32) ^ bMsk[nt]));
#pragma unroll
            for (int mt = 0; mt < 4; mt++)
#pragma unroll
                for (int nt = 0; nt < 4; nt++)
                    mma_bf16(acc[mt][nt], a[mt], b[nt]);
        }
        __syncthreads();
    }

    float* sOut = (float*)smc;
#pragma unroll
    for (int mt = 0; mt < 4; mt++)
#pragma unroll
        for (int nt = 0; nt < 4; nt++) {
            int r0 = wm + mt * 16 + (l >> 2);
            int c  = wn + nt * 8 + (l & 3) * 2;
            *(float2*)&sOut[r0 * 132 + c]       = make_float2(acc[mt][nt][0], acc[mt][nt][1]);
            *(float2*)&sOut[(r0 + 8) * 132 + c] = make_float2(acc[mt][nt][2], acc[mt][nt][3]);
        }
    __syncthreads();

#pragma unroll
    for (int i = 0; i < 16; i++) {
        int fi = tid + 256 * i;
        int row = fi >> 5;
        int c4 = (fi & 31) << 2;
        const int grow = bm + row;
        const int gc = bn + c4;
        float4 v = *(const float4*)&sOut[row * 132 + c4];
        float4 bs = *(const float4*)(bias + gc);
        float vv[4] = {v.x + bs.x, v.y + bs.y, v.z + bs.z, v.w + bs.w};

        if (EPI == 0) {
#pragma unroll
            for (int e = 0; e < 4; e++) vv[e] = tanhf(vv[e]);
        } else if (EPI == 1 || EPI == 3) {
            if (gc >= 64) {
#pragma unroll
                for (int e = 0; e < 4; e++) vv[e] = -softplusf(vv[e]);
            }
            float m1 = mask1[grow];
#pragma unroll
            for (int e = 0; e < 4; e++) vv[e] *= m1;
            if (EPI == 3) {
                float m2 = mask2[grow];
                float4 ax = *(const float4*)(aux + (size_t)grow * 128 + gc);
                vv[0] = m2 * (ax.x + vv[0]); vv[1] = m2 * (ax.y + vv[1]);
                vv[2] = m2 * (ax.z + vv[2]); vv[3] = m2 * (ax.w + vv[3]);
            }
        }

        if (EPI == 0 || EPI == 1) {
            __nv_bfloat16 hb[4], lb[4];
#pragma unroll
            for (int e = 0; e < 4; e++) bf_split(vv[e], hb[e], lb[e]);
            uint2 hi4 = make_uint2(packbf(__bfloat162float(hb[0]), __bfloat162float(hb[1])),
                                   packbf(__bfloat162float(hb[2]), __bfloat162float(hb[3])));
            uint2 lo4 = make_uint2(packbf(__bfloat162float(lb[0]), __bfloat162float(lb[1])),
                                   packbf(__bfloat162float(lb[2]), __bfloat162float(lb[3])));
            __nv_bfloat16* o = outH + (size_t)grow * (2 * KO) + gc;
            *(uint2*)(o)      = hi4;
            *(uint2*)(o + KO) = lo4;
        }
        if (EPI != 0) {
            *(float4*)(outF + (size_t)grow * Nn + gc) =
                make_float4(vv[0], vv[1], vv[2], vv[3]);
        }
    }
}

// ---------------- GRU: 3 phases, Ug column-resident, f32x2 dots; writes hs2 dual ----------------
__global__ void __launch_bounds__(384, 1) gru_kernel(const float* __restrict__ Ug, int n0) {
    const int n = n0 + blockIdx.x;
    const int j = threadIdx.x;
    __shared__ __align__(16) float h[128];
    __shared__ float rbuf[128], zbuf[128], nbuf[128];
    u64 ug2[64];
#pragma unroll
    for (int k2 = 0; k2 < 64; k2++)
        ug2[k2] = pk2(Ug[(2 * k2) * 384 + j], Ug[(2 * k2 + 1) * 384 + j]);
    if (j < 128) h[j] = 0.0f;

    const float* gbase = g_gall + (size_t)n * T_ * 384;
    float gv = gbase[j];
    __syncthreads();
    for (int t = 0; t < T_; t++) {
        float gvn = 0.0f;
        if (t + 1 < T_) gvn = gbase[(size_t)(t + 1) * 384 + j];

        u64 s4[4] = {0ULL, 0ULL, 0ULL, 0ULL};
#pragma unroll
        for (int k = 0; k < 128; k += 8) {
            ulonglong2 h0 = *(const ulonglong2*)&h[k];
            ulonglong2 h1 = *(const ulonglong2*)&h[k + 4];
            s4[0] = fma2(h0.x, ug2[k / 2],     s4[0]);
            s4[1] = fma2(h0.y, ug2[k / 2 + 1], s4[1]);
            s4[2] = fma2(h1.x, ug2[k / 2 + 2], s4[2]);
            s4[3] = fma2(h1.y, ug2[k / 2 + 3], s4[3]);
        }
        float2 f0 = upk(s4[0]), f1 = upk(s4[1]), f2 = upk(s4[2]), f3 = upk(s4[3]);
        float s = ((f0.x + f0.y) + (f1.x + f1.y)) + ((f2.x + f2.y) + (f3.x + f3.y));
        if (j < 256) {
            float val = 1.0f / (1.0f + expf(-(gv + s)));
            if (j < 128) rbuf[j] = val; else zbuf[j - 128] = val;
        }
        __syncthreads();
        if (j >= 256) {
            nbuf[j - 256] = tanhf(gv + rbuf[j - 256] * s);
        }
        __syncthreads();
        if (j < 128) {
            float z = zbuf[j];
            float hn = (1.0f - z) * nbuf[j] + z * h[j];
            h[j] = hn;
            __nv_bfloat16 hi, lo; bf_split(hn, hi, lo);
            size_t rb = (size_t)(n * T_ + t) * 256;
            g_hs2[rb + j] = hi; g_hs2[rb + 128 + j] = lo;
        }
        gv = gvn;
        __syncthreads();
    }
}

// ---------------- filter: 3 barriers/step; noise precomputed; u in regs ----------------
__global__ void __launch_bounds__(256, 1) filter_kernel(
    const float* __restrict__ u, const float* __restrict__ Wd1,
    const float* __restrict__ bd1, const float* __restrict__ Wd2,
    const float* __restrict__ bd2, const float* __restrict__ logQ,
    float* __restrict__ out, int n0)
{
    const int n = n0 + blockIdx.x;
    const int tid = threadIdx.x;
    const int q = tid >> 6, j = tid & 63;
    __shared__ __align__(16) float xbuf[64];     // m only
    __shared__ __align__(16) float hdyn[256];
    __shared__ float part[4][64];

    u64 wc2[36];
#pragma unroll
    for (int m = 0; m < 36; m++)
        wc2[m] = pk2(Wd1[(2 * m) * 256 + tid], Wd1[(2 * m + 1) * 256 + tid]);
    u64 w2[32];
#pragma unroll
    for (int m = 0; m < 32; m++)
        w2[m] = pk2(Wd2[(q * 64 + 2 * m) * 64 + j], Wd2[(q * 64 + 2 * m + 1) * 64 + j]);
    const float bd1v = bd1[tid];
    const float bd2j = bd2[j];
    const float Qj = softplusf(logQ[j]);
    float vcur = 1.0f;

    if (tid < 64) xbuf[tid] = 0.0f;

    float* outZ = out;
    float* outS = out + (size_t)NT_ * 64;
    float* outP = out + (size_t)NT_ * 192;

    const size_t base = (size_t)n * T_;
    float a1c = 0.0f, a2c = 0.0f, noic = 0.0f;
    if (tid < 64) {
        a1c = g_ab[base * 128 + j];
        a2c = g_ab[base * 128 + 64 + j];
        noic = g_noise[base * 64 + j];
    }
    float4 u8a = *(const float4*)(u + base * 8);
    float4 u8b = *(const float4*)(u + base * 8 + 4);
    __syncthreads();

    for (int t = 0; t < T_; t++) {
        const size_t row = base + t;

        float a1n = 0.0f, a2n = 0.0f, noin = 0.0f;
        float4 u8an = make_float4(0, 0, 0, 0), u8bn = make_float4(0, 0, 0, 0);
        if (t + 1 < T_) {
            if (tid < 64) {
                a1n = g_ab[(row + 1) * 128 + j];
                a2n = g_ab[(row + 1) * 128 + 64 + j];
                noin = g_noise[(row + 1) * 64 + j];
            }
            u8an = *(const float4*)(u + (row + 1) * 8);
            u8bn = *(const float4*)(u + (row + 1) * 8 + 4);
        }

        u64 s2a = pk2(bd1v, 0.0f), s2b = 0ULL;
#pragma unroll
        for (int k = 0; k < 64; k += 4) {
            ulonglong2 xv = *(const ulonglong2*)&xbuf[k];
            s2a = fma2(xv.x, wc2[k / 2],     s2a);
            s2b = fma2(xv.y, wc2[k / 2 + 1], s2b);
        }
        s2a = fma2(pk2(u8a.x, u8a.y), wc2[32], s2a);
        s2b = fma2(pk2(u8a.z, u8a.w), wc2[33], s2b);
        s2a = fma2(pk2(u8b.x, u8b.y), wc2[34], s2a);
        s2b = fma2(pk2(u8b.z, u8b.w), wc2[35], s2b);
        {
            float2 fa = upk(s2a), fb = upk(s2b);
            hdyn[tid] = tanhf((fa.x + fa.y) + (fb.x + fb.y));
        }
        __syncthreads();

        u64 p2a = 0ULL, p2b = 0ULL;
#pragma unroll
        for (int k = 0; k < 64; k += 4) {
            ulonglong2 hv = *(const ulonglong2*)&hdyn[q * 64 + k];
            p2a = fma2(hv.x, w2[k / 2],     p2a);
            p2b = fma2(hv.y, w2[k / 2 + 1], p2b);
        }
        {
            float2 fa = upk(p2a), fb = upk(p2b);
            part[q][j] = (fa.x + fa.y) + (fb.x + fb.y);
        }
        __syncthreads();

        if (tid < 64) {
            float mp = ((part[0][j] + part[1][j]) + (part[2][j] + part[3][j])) + bd2j;
            float vp = vcur + Qj;
            float Jp = 1.0f / vp;
            float hp = mp * Jp;
            float Jpost = Jp - 2.0f * a2c;
            float vn = 1.0f / Jpost;
            float mn = (hp + a1c) * vn;
            float zz = mn + sqrtf(vn) * noic;
            xbuf[j] = mn;
            vcur = vn;
            outZ[row * 64 + j] = zz;
            outS[row * 128 + j] = mn;
            outS[row * 128 + 64 + j] = vn;
            outP[row * 128 + j] = mp;
            outP[row * 128 + 64 + j] = vp;
            a1c = a1n; a2c = a2n; noic = noin;
        }
        u8a = u8an; u8b = u8bn;
        __syncthreads();
    }
}

// ---------------- host launcher ----------------
extern "C" void kernel_launch(void* const* d_in, const int* in_sizes, int n_in,
                              void* d_out, int out_size) {
    (void)in_sizes; (void)n_in; (void)out_size;
    const int*   seed    = (const int*)d_in[3];
    const float* dropout = (const float*)d_in[4];
    const float* y   = (const float*)d_in[1];
    const float* u   = (const float*)d_in[2];
    const float* W1  = (const float*)d_in[5];
    const float* b1  = (const float*)d_in[6];
    const float* W2  = (const float*)d_in[7];
    const float* b2  = (const float*)d_in[8];
    const float* Wg  = (const float*)d_in[9];
    const float* Ug  = (const float*)d_in[10];
    const float* bg  = (const float*)d_in[11];
    const float* Wo  = (const float*)d_in[12];
    const float* bo  = (const float*)d_in[13];
    const float* Wd1 = (const float*)d_in[14];
    const float* bd1 = (const float*)d_in[15];
    const float* Wd2 = (const float*)d_in[16];
    const float* bd2 = (const float*)d_in[17];
    const float* logQ= (const float*)d_in[18];
    float* out = (float*)d_out;

    float *pa, *pg, *pab, *pmA, *pmB, *pmAB;
    __nv_bfloat16 *py2, *ph2, *pa2, *phs2, *pW1t, *pW2t, *pWgt, *pWot;
    cudaGetSymbolAddress((void**)&pa,   g_a);
    cudaGetSymbolAddress((void**)&pg,   g_gall);
    cudaGetSymbolAddress((void**)&pab,  g_ab);
    cudaGetSymbolAddress((void**)&pmA,  g_maskA);
    cudaGetSymbolAddress((void**)&pmB,  g_maskB);
    cudaGetSymbolAddress((void**)&pmAB, g_maskAB);
    cudaGetSymbolAddress((void**)&py2,  g_y2);
    cudaGetSymbolAddress((void**)&ph2,  g_h2);
    cudaGetSymbolAddress((void**)&pa2,  g_a2);
    cudaGetSymbolAddress((void**)&phs2, g_hs2);
    cudaGetSymbolAddress((void**)&pW1t, g_W1t);
    cudaGetSymbolAddress((void**)&pW2t, g_W2t);
    cudaGetSymbolAddress((void**)&pWgt, g_Wgt);
    cudaGetSymbolAddress((void**)&pWot, g_Wot);

    // EXACTLY 3 side streams (the count that passed the allocation guard in R11)
    static cudaStream_t s_chain = nullptr, sG = nullptr, sF = nullptr;
    static cudaEvent_t ev_fork = nullptr, ev_join = nullptr;
    static cudaEvent_t evGemm[NCH], evDone[NCH];
    if (s_chain == nullptr) {
        cudaStreamCreateWithFlags(&s_chain, cudaStreamNonBlocking);
        cudaStreamCreateWithFlags(&sG, cudaStreamNonBlocking);
        cudaStreamCreateWithFlags(&sF, cudaStreamNonBlocking);
        cudaEventCreateWithFlags(&ev_fork, cudaEventDisableTiming);
        cudaEventCreateWithFlags(&ev_join, cudaEventDisableTiming);
        for (int c = 0; c < NCH; c++) {
            cudaEventCreateWithFlags(&evGemm[c], cudaEventDisableTiming);
            cudaEventCreateWithFlags(&evDone[c], cudaEventDisableTiming);
        }
        cudaFuncSetAttribute(tgemm_k<0>, cudaFuncAttributeMaxDynamicSharedMemorySize, TG_SMEM);
        cudaFuncSetAttribute(tgemm_k<1>, cudaFuncAttributeMaxDynamicSharedMemorySize, TG_SMEM);
        cudaFuncSetAttribute(tgemm_k<2>, cudaFuncAttributeMaxDynamicSharedMemorySize, TG_SMEM);
        cudaFuncSetAttribute(tgemm_k<3>, cudaFuncAttributeMaxDynamicSharedMemorySize, TG_SMEM);
    }

    key_kernel<<<1, 1>>>(seed, dropout);

    // fork: serial Threefry chain + full noise precompute on side stream
    cudaEventRecord(ev_fork, 0);
    cudaStreamWaitEvent(s_chain, ev_fork, 0);
    chain_kernel<<<1, 128, 0, s_chain>>>();
    noise_kernel<<<(NT_ * 64) / 256, 256, 0, s_chain>>>();
    cudaEventRecord(ev_join, s_chain);

    mask_kernel<<<(NT_ + 255) / 256, 256>>>();
    conv_w_k<<<(DO_ * HE_ + 255) / 256, 256>>>(W1, pW1t, DO_, HE_);
    conv_w_k<<<(HE_ * DN_ + 255) / 256, 256>>>(W2, pW2t, HE_, DN_);
    conv_w_k<<<(DN_ * 384 + 255) / 256, 256>>>(Wg, pWgt, DN_, 384);
    conv_w_k<<<(HG_ * DN_ + 255) / 256, 256>>>(Wo, pWot, HG_, DN_);

    // chunk chains mapped to: {s_chain, sG, sF, default-stream}
    cudaStream_t chainStream[NCH] = {s_chain, sG, sF, (cudaStream_t)0};

    for (int c = 0; c < NCH; c++) {
        const int n0 = c * CHN;
        const int rowoff = n0 * T_;

        // stage A (stream 0): conv_y + 3 GEMMs for this chunk
        conv_y_k<<<CHROW, 256>>>(y, rowoff);
        tgemm_k<0><<<dim3(4, CHROW / 128), 256, TG_SMEM>>>(py2, pW1t, b1, DO_, HE_, HE_, rowoff,
                                                           nullptr, ph2, nullptr, nullptr, nullptr);
        tgemm_k<1><<<dim3(1, CHROW / 128), 256, TG_SMEM>>>(ph2, pW2t, b2, HE_, DN_, DN_, rowoff,
                                                           pa, pa2, pmA, nullptr, nullptr);
        tgemm_k<2><<<dim3(3, CHROW / 128), 256, TG_SMEM>>>(pa2, pWgt, bg, DN_, 384, 0, rowoff,
                                                           pg, nullptr, nullptr, nullptr, nullptr);

        cudaStream_t sc = chainStream[c];
        if (sc != (cudaStream_t)0) {
            cudaEventRecord(evGemm[c], 0);
            cudaStreamWaitEvent(sc, evGemm[c], 0);
        }
        // stages B+C: GRU -> tgemm3 -> filter on this chunk's lane
        gru_kernel<<<CHN, 384, 0, sc>>>(Ug, n0);
        tgemm_k<3><<<dim3(1, CHROW / 128), 256, TG_SMEM, sc>>>(phs2, pWot, bo, HG_, DN_, 0, rowoff,
                                                               pab, nullptr, pmB, pmAB, pa);
        cudaStreamWaitEvent(sc, ev_join, 0);   // noise ready before filter
        filter_kernel<<<CHN, 256, 0, sc>>>(u, Wd1, bd1, Wd2, bd2, logQ, out, n0);
        if (sc != (cudaStream_t)0) cudaEventRecord(evDone[c], sc);
    }

    // join side-stream chains back into the capture stream
    for (int c = 0; c < NCH - 1; c++)
        cudaStreamWaitEvent(0, evDone[c], 0);
}

// round 14
// speedup vs baseline: 2.0477x; 1.1996x over previous
#include <cuda_runtime.h>
#include <cuda_bf16.h>
#include <cstdint>
#include <math.h>

#define N_  128
#define T_  1000
#define DO_ 256
#define DS_ 64
#define DU_ 8
#define HE_ 512
#define HG_ 128
#define HD_ 256
#define DN_ 128
#define NT_ (N_*T_)

typedef unsigned long long u64;

// ---------------- f32x2 packed helpers (GRU/filter) ----------------
__device__ __forceinline__ u64 pk2(float lo, float hi) {
    u64 r; asm("mov.b64 %0, {%1, %2};" : "=l"(r) : "f"(lo), "f"(hi)); return r;
}
__device__ __forceinline__ u64 fma2(u64 a, u64 b, u64 c) {
    u64 d; asm("fma.rn.f32x2 %0, %1, %2, %3;" : "=l"(d) : "l"(a), "l"(b), "l"(c)); return d;
}
__device__ __forceinline__ float2 upk(u64 v) {
    float2 f; asm("mov.b64 {%0, %1}, %2;" : "=f"(f.x), "=f"(f.y) : "l"(v)); return f;
}

// ---------------- cp.async ----------------
__device__ __forceinline__ void cp_async16(uint32_t saddr, const void* gptr) {
    asm volatile("cp.async.cg.shared.global [%0], [%1], 16;" :: "r"(saddr), "l"(gptr));
}
__device__ __forceinline__ void cp_commit() { asm volatile("cp.async.commit_group;"); }

__device__ __forceinline__ uint32_t smem_u32(const void* p) {
    uint32_t a;
    asm("{ .reg .u64 t; cvta.to.shared.u64 t, %1; cvt.u32.u64 %0, t; }" : "=r"(a) : "l"(p));
    return a;
}

// ---------------- mma.sync bf16 helpers ----------------
__device__ __forceinline__ void ldsm_x4(uint32_t& r0, uint32_t& r1, uint32_t& r2, uint32_t& r3,
                                        uint32_t addr) {
    asm volatile("ldmatrix.sync.aligned.m8n8.x4.shared.b16 {%0,%1,%2,%3}, [%4];"
                 : "=r"(r0), "=r"(r1), "=r"(r2), "=r"(r3) : "r"(addr));
}
__device__ __forceinline__ void ldsm_x2(uint32_t& r0, uint32_t& r1, uint32_t addr) {
    asm volatile("ldmatrix.sync.aligned.m8n8.x2.shared.b16 {%0,%1}, [%2];"
                 : "=r"(r0), "=r"(r1) : "r"(addr));
}
__device__ __forceinline__ void mma_bf16(float* d, const uint32_t* a, const uint32_t* b) {
    asm volatile("mma.sync.aligned.m16n8k16.row.col.f32.bf16.bf16.f32 "
                 "{%0,%1,%2,%3}, {%4,%5,%6,%7}, {%8,%9}, {%0,%1,%2,%3};"
                 : "+f"(d[0]), "+f"(d[1]), "+f"(d[2]), "+f"(d[3])
                 : "r"(a[0]), "r"(a[1]), "r"(a[2]), "r"(a[3]), "r"(b[0]), "r"(b[1]));
}

// ---------------- scratch ----------------
__device__ __nv_bfloat16 g_y2[(size_t)NT_ * 512];     // y  dual [hi|lo]
__device__ __nv_bfloat16 g_h2[(size_t)NT_ * 1024];    // h  dual
__device__ __nv_bfloat16 g_a2[(size_t)NT_ * 256];     // a  dual
__device__ __nv_bfloat16 g_hs2[(size_t)NT_ * 256];    // hs dual
__device__ __nv_bfloat16 g_W1t[512 * 768];            // B triple [hi|lo|hi]
__device__ __nv_bfloat16 g_W2t[128 * 1536];
__device__ __nv_bfloat16 g_Wgt[384 * 256 * 3 / 2];    // 384*384
__device__ __nv_bfloat16 g_Wot[128 * 384];
__device__ float g_a[(size_t)NT_ * DN_];
__device__ float g_gall[(size_t)NT_ * 3 * HG_];
__device__ float g_ab[(size_t)NT_ * DN_];
__device__ float g_noise[(size_t)NT_ * 64];           // precomputed gaussian noise
__device__ float g_maskA[NT_];
__device__ float g_maskB[NT_];
__device__ float g_maskAB[NT_];
__device__ unsigned int g_skeys[(size_t)NT_ * 2];
__device__ unsigned int g_keys[8];
__device__ float g_p;

// ---------------- Threefry2x32 ----------------
__device__ __forceinline__ void tf_round(unsigned int& x0, unsigned int& x1, int r) {
    x0 += x1;
    x1 = __funnelshift_l(x1, x1, r);
    x1 ^= x0;
}
__device__ __forceinline__ uint2 tf2x32(unsigned int k0, unsigned int k1,
                                        unsigned int c0, unsigned int c1) {
    unsigned int ks2 = k0 ^ k1 ^ 0x1BD11BDAu;
    unsigned int x0 = c0 + k0;
    unsigned int x1 = c1 + k1;
    tf_round(x0,x1,13); tf_round(x0,x1,15); tf_round(x0,x1,26); tf_round(x0,x1,6);
    x0 += k1;  x1 += ks2 + 1u;
    tf_round(x0,x1,17); tf_round(x0,x1,29); tf_round(x0,x1,16); tf_round(x0,x1,24);
    x0 += ks2; x1 += k0 + 2u;
    tf_round(x0,x1,13); tf_round(x0,x1,15); tf_round(x0,x1,26); tf_round(x0,x1,6);
    x0 += k0;  x1 += k1 + 3u;
    tf_round(x0,x1,17); tf_round(x0,x1,29); tf_round(x0,x1,16); tf_round(x0,x1,24);
    x0 += k1;  x1 += ks2 + 4u;
    tf_round(x0,x1,13); tf_round(x0,x1,15); tf_round(x0,x1,26); tf_round(x0,x1,6);
    x0 += ks2; x1 += k0 + 5u;
    return make_uint2(x0, x1);
}
__device__ __forceinline__ float bits_to_unit(unsigned int bits) {
    return __uint_as_float((bits >> 9) | 0x3f800000u) - 1.0f;
}
__device__ __forceinline__ float softplusf(float x) {
    return fmaxf(x, 0.0f) + log1pf(expf(-fabsf(x)));
}
__device__ __forceinline__ void bf_split(float v, __nv_bfloat16& hi, __nv_bfloat16& lo) {
    hi = __float2bfloat16(v);
    lo = __float2bfloat16(v - __bfloat162float(hi));
}
__device__ __forceinline__ uint32_t packbf(float x, float y) {
    __nv_bfloat162 h = __floats2bfloat162_rn(x, y);
    return *(uint32_t*)&h;
}

// ---------------- key derivation ----------------
__global__ void key_kernel(const int* seed, const float* dropout) {
    if (threadIdx.x == 0 && blockIdx.x == 0) {
        unsigned int k0 = 0u, k1 = (unsigned int)seed[0];
        uint2 keyF = tf2x32(k0, k1, 0u, 0u);
        uint2 enc  = tf2x32(k0, k1, 0u, 1u);
        uint2 kA = tf2x32(enc.x, enc.y, 0u, 0u);
        uint2 s1 = tf2x32(enc.x, enc.y, 0u, 1u);
        uint2 kB = tf2x32(s1.x, s1.y, 0u, 0u);
        uint2 s2 = tf2x32(s1.x, s1.y, 0u, 1u);
        uint2 kAB = tf2x32(s2.x, s2.y, 0u, 0u);
        g_keys[0] = kA.x;  g_keys[1] = kA.y;
        g_keys[2] = kB.x;  g_keys[3] = kB.y;
        g_keys[4] = kAB.x; g_keys[5] = kAB.y;
        g_keys[6] = keyF.x; g_keys[7] = keyF.y;
        g_p = 1.0f - dropout[0];
    }
}

// ---------------- bernoulli masks ----------------
__global__ void mask_kernel() {
    int idx = blockIdx.x * blockDim.x + threadIdx.x;
    if (idx >= NT_) return;
    float p = g_p;
    unsigned int ci = (unsigned int)idx;
    uint2 ra = tf2x32(g_keys[0], g_keys[1], 0u, ci);
    uint2 rb = tf2x32(g_keys[2], g_keys[3], 0u, ci);
    uint2 rc = tf2x32(g_keys[4], g_keys[5], 0u, ci);
    g_maskA[idx]  = (bits_to_unit(ra.x ^ ra.y) < p) ? 1.0f : 0.0f;
    g_maskB[idx]  = (bits_to_unit(rb.x ^ rb.y) < p) ? 1.0f : 0.0f;
    g_maskAB[idx] = (bits_to_unit(rc.x ^ rc.y) < p) ? 1.0f : 0.0f;
}

// ---------------- serial key chain (side stream) ----------------
__global__ void chain_kernel() {
    int n = blockIdx.x * blockDim.x + threadIdx.x;
    if (n >= N_) return;
    uint2 kk = tf2x32(g_keys[6], g_keys[7], 0u, (unsigned int)n);
    for (int t = 0; t < T_; t++) {
        uint2 sk = tf2x32(kk.x, kk.y, 0u, 1u);
        uint2 nk = tf2x32(kk.x, kk.y, 0u, 0u);
        size_t row = (size_t)n * T_ + t;
        g_skeys[row * 2 + 0] = sk.x;
        g_skeys[row * 2 + 1] = sk.y;
        kk = nk;
    }
}

// ---------------- noise precompute (side stream; off filter's critical path) ----------------
__global__ void noise_kernel() {
    size_t idx = (size_t)blockIdx.x * 256 + threadIdx.x;   // NT*64 total
    size_t row = idx >> 6;
    unsigned int j = (unsigned int)(idx & 63);
    uint2 r = tf2x32(g_skeys[row * 2], g_skeys[row * 2 + 1], 0u, j);
    float f = bits_to_unit(r.x ^ r.y);
    float uu = __fadd_rn(__fmul_rn(f, 2.0f), -0.99999994f);
    uu = fmaxf(uu, -0.99999994f);
    g_noise[idx] = 1.41421356f * erfinvf(uu);
}

// ---------------- conversions ----------------
__global__ void conv_y_k(const float* __restrict__ y) {
    int idx = blockIdx.x * 256 + threadIdx.x;
    int m = idx >> 8, k = idx & 255;
    float v = y[(size_t)m * 256 + k];
    __nv_bfloat16 hi, lo; bf_split(v, hi, lo);
    size_t rb = (size_t)m * 512;
    g_y2[rb + k] = hi; g_y2[rb + 256 + k] = lo;
}
__global__ void conv_w_k(const float* __restrict__ W, __nv_bfloat16* __restrict__ Wt,
                         int K, int Nn) {
    int idx = blockIdx.x * 256 + threadIdx.x;
    if (idx >= K * Nn) return;
    int k = idx / Nn, n = idx % Nn;
    float v = W[idx];
    __nv_bfloat16 hi, lo; bf_split(v, hi, lo);
    size_t rb = (size_t)n * 3 * K;
    Wt[rb + k] = hi; Wt[rb + K + k] = lo; Wt[rb + 2 * K + k] = hi;
}

// ---------------- HMMA bf16-split GEMM (128x128 tile/CTA, mma.sync) ----------------
// A stored dual [M][2K]; logical 64-block ko -> phys (ko<K ? ko : ko-K). B triple [Nn][3K].
#define TG_SMEM (128 * 132 * 4)   // 67584

template <int EPI>
__global__ void __launch_bounds__(256, 2) tgemm_k(
    const __nv_bfloat16* __restrict__ A2, const __nv_bfloat16* __restrict__ B2,
    const float* __restrict__ bias, int Ka, int Nn, int KO,
    float* __restrict__ outF, __nv_bfloat16* __restrict__ outH,
    const float* __restrict__ mask1, const float* __restrict__ mask2,
    const float* __restrict__ aux)
{
    extern __shared__ __align__(16) char smc[];
    const uint32_t sb = smem_u32(smc);
    const int tid = threadIdx.x;
    const int bm = blockIdx.y * 128, bn = blockIdx.x * 128;
    const int Kp = 3 * Ka;
    const int Kpa = 2 * Ka;

    uint32_t dsw[4];
    const __nv_bfloat16 *srcA[4], *srcB[4];
#pragma unroll
    for (int i = 0; i < 4; i++) {
        int g = tid + 256 * i;
        int row = g >> 3, c = g & 7;
        uint32_t off = (uint32_t)(row * 128 + c * 16);
        dsw[i] = off ^ ((off >> 3) & 0x70);
        srcA[i] = A2 + (size_t)(bm + row) * Kpa + c * 8;
        srcB[i] = B2 + (size_t)(bn + row) * Kp + c * 8;
    }
    const int KB = Kp >> 6;

    const int w = tid >> 5, l = tid & 31;
    const int wm = (w & 1) * 64, wn = (w >> 1) * 32;

    uint32_t aOff[4], aMsk[4];
#pragma unroll
    for (int mt = 0; mt < 4; mt++) {
        int row = wm + mt * 16 + (l & 15);
        aOff[mt] = (uint32_t)(row * 128 + (l >> 4) * 16);
        aMsk[mt] = ((uint32_t)(row & 7)) << 4;
    }
    uint32_t bOff[4], bMsk[4];
#pragma unroll
    for (int nt = 0; nt < 4; nt++) {
        int row = wn + nt * 8 + (l & 7);
        bOff[nt] = (uint32_t)(row * 128 + ((l >> 3) & 1) * 16);
        bMsk[nt] = ((uint32_t)(row & 7)) << 4;
    }

    float acc[4][4][4];
#pragma unroll
    for (int mt = 0; mt < 4; mt++)
#pragma unroll
        for (int nt = 0; nt < 4; nt++)
#pragma unroll
            for (int e = 0; e < 4; e++) acc[mt][nt][e] = 0.0f;

#pragma unroll
    for (int i = 0; i < 4; i++) cp_async16(sb + dsw[i], srcA[i]);
#pragma unroll
    for (int i = 0; i < 4; i++) cp_async16(sb + 16384 + dsw[i], srcB[i]);
    cp_commit();

    for (int kb = 0; kb < KB; kb++) {
        const int s = kb & 1;
        if (kb + 1 < KB) {
            uint32_t base = sb + (uint32_t)(s ^ 1) * 32768;
            const int ko = (kb + 1) * 64;
            const int pko = (ko < Ka) ? ko : (ko - Ka);
#pragma unroll
            for (int i = 0; i < 4; i++) cp_async16(base + dsw[i], srcA[i] + pko);
#pragma unroll
            for (int i = 0; i < 4; i++) cp_async16(base + 16384 + dsw[i], srcB[i] + ko);
            cp_commit();
            asm volatile("cp.async.wait_group 1;" ::: "memory");
        } else {
            asm volatile("cp.async.wait_group 0;" ::: "memory");
        }
        __syncthreads();

        const uint32_t aB = sb + (uint32_t)s * 32768;
        const uint32_t bB = aB + 16384;
#pragma unroll
        for (int ks = 0; ks < 4; ks++) {
            uint32_t a[4][4], b[4][2];
#pragma unroll
            for (int mt = 0; mt < 4; mt++)
                ldsm_x4(a[mt][0], a[mt][1], a[mt][2], a[mt][3],
                        aB + ((aOff[mt] + ks * 32) ^ aMsk[mt]));
#pragma unroll
            for (int nt = 0; nt < 4; nt++)
                ldsm_x2(b[nt][0], b[nt][1],
                        bB + ((bOff[nt] + ks * 32) ^ bMsk[nt]));
#pragma unroll
            for (int mt = 0; mt < 4; mt++)
#pragma unroll
                for (int nt = 0; nt < 4; nt++)
                    mma_bf16(acc[mt][nt], a[mt], b[nt]);
        }
        __syncthreads();
    }

    float* sOut = (float*)smc;
#pragma unroll
    for (int mt = 0; mt < 4; mt++)
#pragma unroll
        for (int nt = 0; nt < 4; nt++) {
            int r0 = wm + mt * 16 + (l >> 2);
            int c  = wn + nt * 8 + (l & 3) * 2;
            *(float2*)&sOut[r0 * 132 + c]       = make_float2(acc[mt][nt][0], acc[mt][nt][1]);
            *(float2*)&sOut[(r0 + 8) * 132 + c] = make_float2(acc[mt][nt][2], acc[mt][nt][3]);
        }
    __syncthreads();

#pragma unroll
    for (int i = 0; i < 16; i++) {
        int fi = tid + 256 * i;
        int row = fi >> 5;
        int c4 = (fi & 31) << 2;
        const int grow = bm + row;
        const int gc = bn + c4;
        float4 v = *(const float4*)&sOut[row * 132 + c4];
        float4 bs = *(const float4*)(bias + gc);
        float vv[4] = {v.x + bs.x, v.y + bs.y, v.z + bs.z, v.w + bs.w};

        if (EPI == 0) {
#pragma unroll
            for (int e = 0; e < 4; e++) vv[e] = tanhf(vv[e]);
        } else if (EPI == 1 || EPI == 3) {
            if (gc >= 64) {
#pragma unroll
                for (int e = 0; e < 4; e++) vv[e] = -softplusf(vv[e]);
            }
            float m1 = mask1[grow];
#pragma unroll
            for (int e = 0; e < 4; e++) vv[e] *= m1;
            if (EPI == 3) {
                float m2 = mask2[grow];
                float4 ax = *(const float4*)(aux + (size_t)grow * 128 + gc);
                vv[0] = m2 * (ax.x + vv[0]); vv[1] = m2 * (ax.y + vv[1]);
                vv[2] = m2 * (ax.z + vv[2]); vv[3] = m2 * (ax.w + vv[3]);
            }
        }

        if (EPI == 0 || EPI == 1) {
            __nv_bfloat16 hb[4], lb[4];
#pragma unroll
            for (int e = 0; e < 4; e++) bf_split(vv[e], hb[e], lb[e]);
            uint2 hi4 = make_uint2(packbf(__bfloat162float(hb[0]), __bfloat162float(hb[1])),
                                   packbf(__bfloat162float(hb[2]), __bfloat162float(hb[3])));
            uint2 lo4 = make_uint2(packbf(__bfloat162float(lb[0]), __bfloat162float(lb[1])),
                                   packbf(__bfloat162float(lb[2]), __bfloat162float(lb[3])));
            __nv_bfloat16* o = outH + (size_t)grow * (2 * KO) + gc;
            *(uint2*)(o)      = hi4;
            *(uint2*)(o + KO) = lo4;
        }
        if (EPI != 0) {
            *(float4*)(outF + (size_t)grow * Nn + gc) =
                make_float4(vv[0], vv[1], vv[2], vv[3]);
        }
    }
}

// ---------------- GRU: 3 phases, Ug column-resident, f32x2 dots; writes hs2 dual ----------------
__global__ void __launch_bounds__(384, 1) gru_kernel(const float* __restrict__ Ug) {
    const int n = blockIdx.x;
    const int j = threadIdx.x;
    __shared__ __align__(16) float h[128];
    __shared__ float rbuf[128], zbuf[128], nbuf[128];
    u64 ug2[64];
#pragma unroll
    for (int k2 = 0; k2 < 64; k2++)
        ug2[k2] = pk2(Ug[(2 * k2) * 384 + j], Ug[(2 * k2 + 1) * 384 + j]);
    if (j < 128) h[j] = 0.0f;

    const float* gbase = g_gall + (size_t)n * T_ * 384;
    float gv = gbase[j];
    __syncthreads();
    for (int t = 0; t < T_; t++) {
        float gvn = 0.0f;
        if (t + 1 < T_) gvn = gbase[(size_t)(t + 1) * 384 + j];

        u64 s4[4] = {0ULL, 0ULL, 0ULL, 0ULL};
#pragma unroll
        for (int k = 0; k < 128; k += 8) {
            ulonglong2 h0 = *(const ulonglong2*)&h[k];
            ulonglong2 h1 = *(const ulonglong2*)&h[k + 4];
            s4[0] = fma2(h0.x, ug2[k / 2],     s4[0]);
            s4[1] = fma2(h0.y, ug2[k / 2 + 1], s4[1]);
            s4[2] = fma2(h1.x, ug2[k / 2 + 2], s4[2]);
            s4[3] = fma2(h1.y, ug2[k / 2 + 3], s4[3]);
        }
        float2 f0 = upk(s4[0]), f1 = upk(s4[1]), f2 = upk(s4[2]), f3 = upk(s4[3]);
        float s = ((f0.x + f0.y) + (f1.x + f1.y)) + ((f2.x + f2.y) + (f3.x + f3.y));
        if (j < 256) {
            float val = 1.0f / (1.0f + expf(-(gv + s)));
            if (j < 128) rbuf[j] = val; else zbuf[j - 128] = val;
        }
        __syncthreads();
        if (j >= 256) {
            nbuf[j - 256] = tanhf(gv + rbuf[j - 256] * s);
        }
        __syncthreads();
        if (j < 128) {
            float z = zbuf[j];
            float hn = (1.0f - z) * nbuf[j] + z * h[j];
            h[j] = hn;
            __nv_bfloat16 hi, lo; bf_split(hn, hi, lo);
            size_t rb = (size_t)(n * T_ + t) * 256;
            g_hs2[rb + j] = hi; g_hs2[rb + 128 + j] = lo;
        }
        gv = gvn;
        __syncthreads();
    }
}

// ---------------- filter: 3 barriers/step; noise precomputed; u in regs ----------------
__global__ void __launch_bounds__(256, 1) filter_kernel(
    const float* __restrict__ u, const float* __restrict__ Wd1,
    const float* __restrict__ bd1, const float* __restrict__ Wd2,
    const float* __restrict__ bd2, const float* __restrict__ logQ,
    float* __restrict__ out)
{
    const int n = blockIdx.x;
    const int tid = threadIdx.x;
    const int q = tid >> 6, j = tid & 63;
    __shared__ __align__(16) float xbuf[64];     // m only
    __shared__ __align__(16) float hdyn[256];
    __shared__ float part[4][64];

    u64 wc2[36];
#pragma unroll
    for (int m = 0; m < 36; m++)
        wc2[m] = pk2(Wd1[(2 * m) * 256 + tid], Wd1[(2 * m + 1) * 256 + tid]);
    u64 w2[32];
#pragma unroll
    for (int m = 0; m < 32; m++)
        w2[m] = pk2(Wd2[(q * 64 + 2 * m) * 64 + j], Wd2[(q * 64 + 2 * m + 1) * 64 + j]);
    const float bd1v = bd1[tid];
    const float bd2j = bd2[j];
    const float Qj = softplusf(logQ[j]);
    float vcur = 1.0f;

    if (tid < 64) xbuf[tid] = 0.0f;

    float* outZ = out;
    float* outS = out + (size_t)NT_ * 64;
    float* outP = out + (size_t)NT_ * 192;

    const size_t base = (size_t)n * T_;
    float a1c = 0.0f, a2c = 0.0f, noic = 0.0f;
    if (tid < 64) {
        a1c = g_ab[base * 128 + j];
        a2c = g_ab[base * 128 + 64 + j];
        noic = g_noise[base * 64 + j];
    }
    float4 u8a = *(const float4*)(u + base * 8);
    float4 u8b = *(const float4*)(u + base * 8 + 4);
    __syncthreads();

    for (int t = 0; t < T_; t++) {
        const size_t row = base + t;

        float a1n = 0.0f, a2n = 0.0f, noin = 0.0f;
        float4 u8an = make_float4(0, 0, 0, 0), u8bn = make_float4(0, 0, 0, 0);
        if (t + 1 < T_) {
            if (tid < 64) {
                a1n = g_ab[(row + 1) * 128 + j];
                a2n = g_ab[(row + 1) * 128 + 64 + j];
                noin = g_noise[(row + 1) * 64 + j];
            }
            u8an = *(const float4*)(u + (row + 1) * 8);
            u8bn = *(const float4*)(u + (row + 1) * 8 + 4);
        }

        u64 s2a = pk2(bd1v, 0.0f), s2b = 0ULL;
#pragma unroll
        for (int k = 0; k < 64; k += 4) {
            ulonglong2 xv = *(const ulonglong2*)&xbuf[k];
            s2a = fma2(xv.x, wc2[k / 2],     s2a);
            s2b = fma2(xv.y, wc2[k / 2 + 1], s2b);
        }
        s2a = fma2(pk2(u8a.x, u8a.y), wc2[32], s2a);
        s2b = fma2(pk2(u8a.z, u8a.w), wc2[33], s2b);
        s2a = fma2(pk2(u8b.x, u8b.y), wc2[34], s2a);
        s2b = fma2(pk2(u8b.z, u8b.w), wc2[35], s2b);
        {
            float2 fa = upk(s2a), fb = upk(s2b);
            hdyn[tid] = tanhf((fa.x + fa.y) + (fb.x + fb.y));
        }
        __syncthreads();

        u64 p2a = 0ULL, p2b = 0ULL;
#pragma unroll
        for (int k = 0; k < 64; k += 4) {
            ulonglong2 hv = *(const ulonglong2*)&hdyn[q * 64 + k];
            p2a = fma2(hv.x, w2[k / 2],     p2a);
            p2b = fma2(hv.y, w2[k / 2 + 1], p2b);
        }
        {
            float2 fa = upk(p2a), fb = upk(p2b);
            part[q][j] = (fa.x + fa.y) + (fb.x + fb.y);
        }
        __syncthreads();

        if (tid < 64) {
            float mp = ((part[0][j] + part[1][j]) + (part[2][j] + part[3][j])) + bd2j;
            float vp = vcur + Qj;
            float Jp = 1.0f / vp;
            float hp = mp * Jp;
            float Jpost = Jp - 2.0f * a2c;
            float vn = 1.0f / Jpost;
            float mn = (hp + a1c) * vn;
            float zz = mn + sqrtf(vn) * noic;
            xbuf[j] = mn;
            vcur = vn;
            outZ[row * 64 + j] = zz;
            outS[row * 128 + j] = mn;
            outS[row * 128 + 64 + j] = vn;
            outP[row * 128 + j] = mp;
            outP[row * 128 + 64 + j] = vp;
            a1c = a1n; a2c = a2n; noic = noin;
        }
        u8a = u8an; u8b = u8bn;
        __syncthreads();
    }
}

// ---------------- host launcher ----------------
extern "C" void kernel_launch(void* const* d_in, const int* in_sizes, int n_in,
                              void* d_out, int out_size) {
    (void)in_sizes; (void)n_in; (void)out_size;
    const int*   seed    = (const int*)d_in[3];
    const float* dropout = (const float*)d_in[4];
    const float* y   = (const float*)d_in[1];
    const float* u   = (const float*)d_in[2];
    const float* W1  = (const float*)d_in[5];
    const float* b1  = (const float*)d_in[6];
    const float* W2  = (const float*)d_in[7];
    const float* b2  = (const float*)d_in[8];
    const float* Wg  = (const float*)d_in[9];
    const float* Ug  = (const float*)d_in[10];
    const float* bg  = (const float*)d_in[11];
    const float* Wo  = (const float*)d_in[12];
    const float* bo  = (const float*)d_in[13];
    const float* Wd1 = (const float*)d_in[14];
    const float* bd1 = (const float*)d_in[15];
    const float* Wd2 = (const float*)d_in[16];
    const float* bd2 = (const float*)d_in[17];
    const float* logQ= (const float*)d_in[18];
    float* out = (float*)d_out;

    float *pa, *pg, *pab, *pmA, *pmB, *pmAB;
    __nv_bfloat16 *py2, *ph2, *pa2, *phs2, *pW1t, *pW2t, *pWgt, *pWot;
    cudaGetSymbolAddress((void**)&pa,   g_a);
    cudaGetSymbolAddress((void**)&pg,   g_gall);
    cudaGetSymbolAddress((void**)&pab,  g_ab);
    cudaGetSymbolAddress((void**)&pmA,  g_maskA);
    cudaGetSymbolAddress((void**)&pmB,  g_maskB);
    cudaGetSymbolAddress((void**)&pmAB, g_maskAB);
    cudaGetSymbolAddress((void**)&py2,  g_y2);
    cudaGetSymbolAddress((void**)&ph2,  g_h2);
    cudaGetSymbolAddress((void**)&pa2,  g_a2);
    cudaGetSymbolAddress((void**)&phs2, g_hs2);
    cudaGetSymbolAddress((void**)&pW1t, g_W1t);
    cudaGetSymbolAddress((void**)&pW2t, g_W2t);
    cudaGetSymbolAddress((void**)&pWgt, g_Wgt);
    cudaGetSymbolAddress((void**)&pWot, g_Wot);

    static cudaStream_t s_chain = nullptr;
    static cudaEvent_t ev_fork = nullptr, ev_join = nullptr;
    if (s_chain == nullptr) {
        cudaStreamCreateWithFlags(&s_chain, cudaStreamNonBlocking);
        cudaEventCreateWithFlags(&ev_fork, cudaEventDisableTiming);
        cudaEventCreateWithFlags(&ev_join, cudaEventDisableTiming);
        cudaFuncSetAttribute(tgemm_k<0>, cudaFuncAttributeMaxDynamicSharedMemorySize, TG_SMEM);
        cudaFuncSetAttribute(tgemm_k<1>, cudaFuncAttributeMaxDynamicSharedMemorySize, TG_SMEM);
        cudaFuncSetAttribute(tgemm_k<2>, cudaFuncAttributeMaxDynamicSharedMemorySize, TG_SMEM);
        cudaFuncSetAttribute(tgemm_k<3>, cudaFuncAttributeMaxDynamicSharedMemorySize, TG_SMEM);
    }

    key_kernel<<<1, 1>>>(seed, dropout);

    // fork: serial Threefry chain + noise precompute overlap the GEMM phase
    cudaEventRecord(ev_fork, 0);
    cudaStreamWaitEvent(s_chain, ev_fork, 0);
    chain_kernel<<<1, 128, 0, s_chain>>>();
    noise_kernel<<<(NT_ * 64) / 256, 256, 0, s_chain>>>();
    cudaEventRecord(ev_join, s_chain);

    mask_kernel<<<(NT_ + 255) / 256, 256>>>();
    conv_y_k<<<NT_, 256>>>(y);
    conv_w_k<<<(DO_ * HE_ + 255) / 256, 256>>>(W1, pW1t, DO_, HE_);
    conv_w_k<<<(HE_ * DN_ + 255) / 256, 256>>>(W2, pW2t, HE_, DN_);
    conv_w_k<<<(DN_ * 384 + 255) / 256, 256>>>(Wg, pWgt, DN_, 384);
    conv_w_k<<<(HG_ * DN_ + 255) / 256, 256>>>(Wo, pWot, HG_, DN_);

    // h = tanh(y @ W1 + b1)            Ka=256, Nn=512 -> h2 dual (KO=512)
    tgemm_k<0><<<dim3(4, 1000), 256, TG_SMEM>>>(py2, pW1t, b1, DO_, HE_, HE_,
                                                nullptr, ph2, nullptr, nullptr, nullptr);
    // a = constrain(h @ W2 + b2)*maskA Ka=512, Nn=128 -> g_a + a2 dual (KO=128)
    tgemm_k<1><<<dim3(1, 1000), 256, TG_SMEM>>>(ph2, pW2t, b2, HE_, DN_, DN_,
                                                pa, pa2, pmA, nullptr, nullptr);
    // g_all = a @ Wg + bg              Ka=128, Nn=384
    tgemm_k<2><<<dim3(3, 1000), 256, TG_SMEM>>>(pa2, pWgt, bg, DN_, 384, 0,
                                                pg, nullptr, nullptr, nullptr, nullptr);
    // GRU scan -> hs2 dual
    gru_kernel<<<N_, 384>>>(Ug);
    // ab = maskAB*(a + constrain(hs @ Wo + bo)*maskB)  Ka=128, Nn=128
    tgemm_k<3><<<dim3(1, 1000), 256, TG_SMEM>>>(phs2, pWot, bo, HG_, DN_, 0,
                                                pab, nullptr, pmB, pmAB, pa);

    // join: filter needs the precomputed noise
    cudaStreamWaitEvent(0, ev_join, 0);
    // filter + sampling
    filter_kernel<<<N_, 256>>>(u, Wd1, bd1, Wd2, bd2, logQ, out);
}